// round 13
// baseline (speedup 1.0000x reference)
#include <cuda_runtime.h>
#include <cuda_fp16.h>
#include <cstdint>

#define NN 50000
#define EE 800000
#define GG 64
#define FF 64
#define BN_EPS 1e-5f

// ---------------- scratch (static device globals; zero-initialized at load) --
// Invariant: d_cnt_in, d_ssum, d_fsum, d_fsq, d_pooled, d_cnt are ZERO at entry
// of every kernel_launch call (static init covers call 1; k_fc tail re-zeros).
__device__ __half d_h[(size_t)NN * FF];    // GEMM output (fp16) / gather source
__device__ float  d_y[(size_t)NN * FF];    // gather output / GEMM input (fp32)
__device__ float  d_s[NN];                 // layer-1 scalar aggregate
__device__ int    d_cnt_in[NN];            // in-degree counters (zeroed in tail)
__device__ int    d_ptr[NN + 1];           // CSR row pointers (by dst)
__device__ int    d_rank[EE];              // per-edge rank within dst row
__device__ int2   d_csr[EE + NN];          // {src, bitcast(norm)}; self incl.
__device__ float  d_ssum[2];               // scalar sum / sumsq (layer 1)
__device__ float  d_fsum[3][FF];           // per-feature sums, layers 2..4
__device__ float  d_fsq[3][FF];
__device__ float  d_pooled[GG * FF];
__device__ float  d_cnt[GG];

// ---------------- setup ------------------------------------------------------
// count AND record rank: the atomic's return value is the edge's slot.
__global__ void k_count(const int* __restrict__ ei, int E_) {
    int e = blockIdx.x * blockDim.x + threadIdx.x;
    if (e < E_) d_rank[e] = atomicAdd(&d_cnt_in[ei[E_ + e]], 1);
}

// single-block exclusive scan of (cnt_in+1) -> d_ptr; tail also writes the
// self-loop CSR entry per row (each thread owns its own prefix — no sync).
__global__ void k_scan() {
    __shared__ int sums[1024];
    int t = threadIdx.x;
    const int CH = (NN + 1023) / 1024;   // 49
    int start = t * CH;
    int end = start + CH; if (end > NN) end = NN;
    int s = 0;
    for (int i = start; i < end; i++) s += d_cnt_in[i] + 1;   // +1 self-loop
    sums[t] = s;
    __syncthreads();
    for (int off = 1; off < 1024; off <<= 1) {
        int v = (t >= off) ? sums[t - off] : 0;
        __syncthreads();
        sums[t] += v;
        __syncthreads();
    }
    int excl = (t == 0) ? 0 : sums[t - 1];
    for (int i = start; i < end; i++) {
        int deg = d_cnt_in[i] + 1;
        d_ptr[i] = excl;
        float di = rsqrtf((float)deg);
        d_csr[excl] = make_int2(i, __float_as_int(di * di));   // self entry
        excl += deg;
    }
    if (t == 1023) d_ptr[NN] = excl;
}

// atomic-free fill: slot = ptr[c] + 1 + rank[e]; norms from cnt_in directly.
__global__ void k_fill(const int* __restrict__ ei, int E_) {
    int e = blockIdx.x * blockDim.x + threadIdx.x;
    if (e >= E_) return;
    int r = ei[e], c = ei[E_ + e];
    float nm = rsqrtf((float)(d_cnt_in[r] + 1)) * rsqrtf((float)(d_cnt_in[c] + 1));
    int p = d_ptr[c] + 1 + d_rank[e];
    d_csr[p] = make_int2(r, __float_as_int(nm));
}

// ---------------- layer 1: scalar gather + fused stats ----------------------
__global__ void k_gather1(const float* __restrict__ x) {
    int n = blockIdx.x * blockDim.x + threadIdx.x;
    float s = 0.f;
    if (n < NN) {
        int p = d_ptr[n], en = d_ptr[n + 1];
        for (; p + 3 < en; p += 4) {
            int2 v0 = __ldg(&d_csr[p]);
            int2 v1 = __ldg(&d_csr[p + 1]);
            int2 v2 = __ldg(&d_csr[p + 2]);
            int2 v3 = __ldg(&d_csr[p + 3]);
            float x0 = __ldg(&x[v0.x]), x1 = __ldg(&x[v1.x]);
            float x2 = __ldg(&x[v2.x]), x3 = __ldg(&x[v3.x]);
            s = fmaf(x0, __int_as_float(v0.y), s);
            s = fmaf(x1, __int_as_float(v1.y), s);
            s = fmaf(x2, __int_as_float(v2.y), s);
            s = fmaf(x3, __int_as_float(v3.y), s);
        }
        for (; p < en; p++) {
            int2 v = __ldg(&d_csr[p]);
            s = fmaf(__ldg(&x[v.x]), __int_as_float(v.y), s);
        }
        d_s[n] = s;
    }
    float q = s * s;
    for (int o = 16; o; o >>= 1) {
        s += __shfl_down_sync(0xffffffffu, s, o);
        q += __shfl_down_sync(0xffffffffu, q, o);
    }
    __shared__ float sh[2][8];
    int w = threadIdx.x >> 5;
    if ((threadIdx.x & 31) == 0) { sh[0][w] = s; sh[1][w] = q; }
    __syncthreads();
    if (threadIdx.x == 0) {
        s = 0.f; q = 0.f;
        for (int i = 0; i < 8; i++) { s += sh[0][i]; q += sh[1][i]; }
        atomicAdd(&d_ssum[0], s);
        atomicAdd(&d_ssum[1], q);
    }
}

// ---------------- GEMM: 128-row tile, fp16 Z in smem, 8x4 micro-tile --------
// d_h = (half) relu(affine(src)) @ W.  src = d_s (FROM_S) or fp32 d_y.
template <bool FROM_S>
__global__ void __launch_bounds__(256) k_gemm(int L, const float* __restrict__ W,
                       const float* __restrict__ Wp,   // W1 (FROM_S only)
                       const float* __restrict__ g, const float* __restrict__ bt) {
    __shared__ __align__(16) __half Zh[FF][144];   // [k][row], stride 288B
    __shared__ __align__(16) float  Ws[FF][FF];    // 16KB
    __shared__ float sa[FF], sc[FF];
    int t = threadIdx.x;
    int base = blockIdx.x * 128;

    if (t < FF) {
        float inv_n = 1.0f / (float)NN;
        if (FROM_S) {
            float ms = d_ssum[0] * inv_n;
            float vs = d_ssum[1] * inv_n - ms * ms;
            float w1 = Wp[t];
            float ia = g[t] * rsqrtf(vs * w1 * w1 + BN_EPS);
            float A = ia * w1;
            sa[t] = A;
            sc[t] = bt[t] - A * ms;
        } else {
            float m = d_fsum[L][t] * inv_n;
            float v = d_fsq[L][t] * inv_n - m * m;
            float ia = g[t] * rsqrtf(v + BN_EPS);
            sa[t] = ia;
            sc[t] = bt[t] - ia * m;
        }
    }
    {
        const float4* W4 = (const float4*)W;
        float4* Ws4 = (float4*)&Ws[0][0];
        #pragma unroll
        for (int i = 0; i < 4; i++) Ws4[t + i * 256] = W4[t + i * 256];
    }
    __syncthreads();

    // stage Z (fp16): 2 threads per row; thread covers 32 cols
    {
        int lr = t >> 1;                    // 0..127
        int row = base + lr;
        int c0 = (t & 1) * 32;
        if (FROM_S) {
            float sval = (row < NN) ? d_s[row] : 0.f;
            #pragma unroll
            for (int i = 0; i < 32; i++) {
                int cc = c0 + i;
                Zh[cc][lr] = __float2half(fmaxf(sa[cc] * sval + sc[cc], 0.f));
            }
        } else if (row < NN) {
            #pragma unroll
            for (int i = 0; i < 8; i++) {
                int cc = c0 + i * 4;
                float4 v = *(const float4*)(d_y + (size_t)row * FF + cc);
                Zh[cc + 0][lr] = __float2half(fmaxf(sa[cc + 0] * v.x + sc[cc + 0], 0.f));
                Zh[cc + 1][lr] = __float2half(fmaxf(sa[cc + 1] * v.y + sc[cc + 1], 0.f));
                Zh[cc + 2][lr] = __float2half(fmaxf(sa[cc + 2] * v.z + sc[cc + 2], 0.f));
                Zh[cc + 3][lr] = __float2half(fmaxf(sa[cc + 3] * v.w + sc[cc + 3], 0.f));
            }
        } else {
            #pragma unroll
            for (int i = 0; i < 32; i++) Zh[c0 + i][lr] = __float2half(0.f);
        }
    }
    __syncthreads();

    int tx = t & 15, ty = t >> 4;
    float acc[8][4] = {};
    #pragma unroll 8
    for (int k = 0; k < FF; k++) {
        uint4 zu = *(const uint4*)&Zh[k][ty * 8];      // 8 halves = 8 rows
        float4 wv = *(const float4*)&Ws[k][tx * 4];
        const __half2* zh = (const __half2*)&zu;
        float2 z0 = __half22float2(zh[0]);
        float2 z1 = __half22float2(zh[1]);
        float2 z2 = __half22float2(zh[2]);
        float2 z3 = __half22float2(zh[3]);
        float zr[8] = {z0.x, z0.y, z1.x, z1.y, z2.x, z2.y, z3.x, z3.y};
        float wc[4] = {wv.x, wv.y, wv.z, wv.w};
        #pragma unroll
        for (int r = 0; r < 8; r++)
            #pragma unroll
            for (int j = 0; j < 4; j++)
                acc[r][j] = fmaf(zr[r], wc[j], acc[r][j]);
    }
    __syncthreads();    // Zh reads done; reuse as fp16 output stage [128][72]

    __half* zbuf = &Zh[0][0];
    #pragma unroll
    for (int r = 0; r < 8; r++) {
        int sr = ty * 8 + r;
        *(__half2*)&zbuf[sr * 72 + tx * 4]     = __floats2half2_rn(acc[r][0], acc[r][1]);
        *(__half2*)&zbuf[sr * 72 + tx * 4 + 2] = __floats2half2_rn(acc[r][2], acc[r][3]);
    }
    __syncthreads();

    {
        int lr = t >> 1;
        int row = base + lr;
        if (row < NN) {
            int seg = (t & 1) * 32;            // 32 halves = 64B
            const uint4* src = (const uint4*)&zbuf[lr * 72 + seg];
            uint4* dst = (uint4*)(d_h + (size_t)row * FF + seg);
            #pragma unroll
            for (int i = 0; i < 4; i++) dst[i] = src[i];
        }
    }
}

// ---------------- 64-wide gather (fp16 source): 16 threads/node --------------
__global__ void k_gather64(int L) {
    __shared__ float4 smS[8][32];
    __shared__ float4 smQ[8][32];
    int t = threadIdx.x;
    int lane = t & 31, w = t >> 5;          // 8 warps / block
    int fl = lane & 15, sub = lane >> 4;
    float4 rS = make_float4(0.f, 0.f, 0.f, 0.f);
    float4 rQ = make_float4(0.f, 0.f, 0.f, 0.f);
    const uint2* hb = (const uint2*)d_h;    // 16 uint2 (8B) per 64-half row

    for (int n = (blockIdx.x * 8 + w) * 2 + sub; n < NN; n += gridDim.x * 16) {
        int p = d_ptr[n], en = d_ptr[n + 1];
        float4 acc = make_float4(0.f, 0.f, 0.f, 0.f);
        for (; p + 3 < en; p += 4) {
            int2 v0 = __ldg(&d_csr[p]);
            int2 v1 = __ldg(&d_csr[p + 1]);
            int2 v2 = __ldg(&d_csr[p + 2]);
            int2 v3 = __ldg(&d_csr[p + 3]);
            uint2 u0 = __ldg(hb + (size_t)v0.x * 16 + fl);
            uint2 u1 = __ldg(hb + (size_t)v1.x * 16 + fl);
            uint2 u2 = __ldg(hb + (size_t)v2.x * 16 + fl);
            uint2 u3 = __ldg(hb + (size_t)v3.x * 16 + fl);
            float m0 = __int_as_float(v0.y), m1 = __int_as_float(v1.y);
            float m2 = __int_as_float(v2.y), m3 = __int_as_float(v3.y);
            float2 a0 = __half22float2(*(__half2*)&u0.x), b0 = __half22float2(*(__half2*)&u0.y);
            float2 a1 = __half22float2(*(__half2*)&u1.x), b1 = __half22float2(*(__half2*)&u1.y);
            float2 a2 = __half22float2(*(__half2*)&u2.x), b2 = __half22float2(*(__half2*)&u2.y);
            float2 a3 = __half22float2(*(__half2*)&u3.x), b3 = __half22float2(*(__half2*)&u3.y);
            acc.x = fmaf(a0.x, m0, acc.x); acc.y = fmaf(a0.y, m0, acc.y);
            acc.z = fmaf(b0.x, m0, acc.z); acc.w = fmaf(b0.y, m0, acc.w);
            acc.x = fmaf(a1.x, m1, acc.x); acc.y = fmaf(a1.y, m1, acc.y);
            acc.z = fmaf(b1.x, m1, acc.z); acc.w = fmaf(b1.y, m1, acc.w);
            acc.x = fmaf(a2.x, m2, acc.x); acc.y = fmaf(a2.y, m2, acc.y);
            acc.z = fmaf(b2.x, m2, acc.z); acc.w = fmaf(b2.y, m2, acc.w);
            acc.x = fmaf(a3.x, m3, acc.x); acc.y = fmaf(a3.y, m3, acc.y);
            acc.z = fmaf(b3.x, m3, acc.z); acc.w = fmaf(b3.y, m3, acc.w);
        }
        for (; p < en; p++) {
            int2 v = __ldg(&d_csr[p]);
            uint2 u0 = __ldg(hb + (size_t)v.x * 16 + fl);
            float m0 = __int_as_float(v.y);
            float2 a0 = __half22float2(*(__half2*)&u0.x), b0 = __half22float2(*(__half2*)&u0.y);
            acc.x = fmaf(a0.x, m0, acc.x); acc.y = fmaf(a0.y, m0, acc.y);
            acc.z = fmaf(b0.x, m0, acc.z); acc.w = fmaf(b0.y, m0, acc.w);
        }
        ((float4*)(d_y + (size_t)n * FF))[fl] = acc;
        rS.x += acc.x; rS.y += acc.y; rS.z += acc.z; rS.w += acc.w;
        rQ.x = fmaf(acc.x, acc.x, rQ.x); rQ.y = fmaf(acc.y, acc.y, rQ.y);
        rQ.z = fmaf(acc.z, acc.z, rQ.z); rQ.w = fmaf(acc.w, acc.w, rQ.w);
    }
    smS[w][lane] = rS; smQ[w][lane] = rQ;
    __syncthreads();
    if (t < 32) {
        float4 s = make_float4(0.f, 0.f, 0.f, 0.f);
        float4 q = make_float4(0.f, 0.f, 0.f, 0.f);
        #pragma unroll
        for (int i = 0; i < 8; i++) {
            float4 a = smS[i][t], b = smQ[i][t];
            s.x += a.x; s.y += a.y; s.z += a.z; s.w += a.w;
            q.x += b.x; q.y += b.y; q.z += b.z; q.w += b.w;
        }
        s.x += __shfl_down_sync(0xffffffffu, s.x, 16);
        s.y += __shfl_down_sync(0xffffffffu, s.y, 16);
        s.z += __shfl_down_sync(0xffffffffu, s.z, 16);
        s.w += __shfl_down_sync(0xffffffffu, s.w, 16);
        q.x += __shfl_down_sync(0xffffffffu, q.x, 16);
        q.y += __shfl_down_sync(0xffffffffu, q.y, 16);
        q.z += __shfl_down_sync(0xffffffffu, q.z, 16);
        q.w += __shfl_down_sync(0xffffffffu, q.w, 16);
        if (t < 16) {
            atomicAdd(&d_fsum[L][4 * t + 0], s.x);
            atomicAdd(&d_fsum[L][4 * t + 1], s.y);
            atomicAdd(&d_fsum[L][4 * t + 2], s.z);
            atomicAdd(&d_fsum[L][4 * t + 3], s.w);
            atomicAdd(&d_fsq[L][4 * t + 0], q.x);
            atomicAdd(&d_fsq[L][4 * t + 1], q.y);
            atomicAdd(&d_fsq[L][4 * t + 2], q.z);
            atomicAdd(&d_fsq[L][4 * t + 3], q.w);
        }
    }
}

// ---------------- pooling (BN4+ReLU inline) ----------------------------------
__global__ void k_pool(const int* __restrict__ batch,
                       const float* __restrict__ g4, const float* __restrict__ bt4) {
    int t = threadIdx.x;
    int f = t & 63, rg = t >> 6;
    int base = blockIdx.x * 256;
    float inv_n = 1.0f / (float)NN;
    float m = d_fsum[2][f] * inv_n;
    float v = d_fsq[2][f] * inv_n - m * m;
    float ia = g4[f] * rsqrtf(v + BN_EPS);
    float af = ia, cf = bt4[f] - ia * m;
    float acc = 0.f, cacc = 0.f;
    int gcur = -1;
    for (int i = 0; i < 64; i++) {
        int n = base + rg + 4 * i;
        if (n >= NN) break;
        int g = batch[n];
        if (g != gcur) {
            if (gcur >= 0) {
                atomicAdd(&d_pooled[gcur * FF + f], acc);
                if (f == 0) atomicAdd(&d_cnt[gcur], cacc);
            }
            gcur = g; acc = 0.f; cacc = 0.f;
        }
        float vv = fmaxf(af * d_y[(size_t)n * FF + f] + cf, 0.f);
        acc += vv; cacc += 1.f;
    }
    if (gcur >= 0) {
        atomicAdd(&d_pooled[gcur * FF + f], acc);
        if (f == 0) atomicAdd(&d_cnt[gcur], cacc);
    }
}

// ---------------- MLP head: one block per graph, transposed fw1 in smem ------
__global__ void k_fc(const float* __restrict__ fw1, const float* __restrict__ fb1,
                     const float* __restrict__ fw2, const float* __restrict__ fb2,
                     float* __restrict__ out) {
    __shared__ float FWt[FF][129];
    __shared__ float P[FF];
    __shared__ float H[128];
    int t = threadIdx.x;               // 128 threads
    int g = blockIdx.x;                // 64 blocks

    for (int idx = t; idx < 128 * FF; idx += 128) {
        int j = idx >> 6, f = idx & 63;
        FWt[f][j] = fw1[idx];
    }
    if (t < FF) {
        float cc = d_cnt[g]; cc = (cc < 1.f) ? 1.f : cc;
        P[t] = d_pooled[g * FF + t] / cc;
    }
    __syncthreads();

    {
        float s = fb1[t];
        #pragma unroll 16
        for (int f = 0; f < FF; f++) s = fmaf(P[f], FWt[f][t], s);
        H[t] = fmaxf(s, 0.f);
    }
    __syncthreads();

    if (t < 10) {
        float s = fb2[t];
        #pragma unroll 16
        for (int j = 0; j < 128; j++) s = fmaf(H[j], fw2[t * 128 + j], s);
        out[g * 10 + t] = s;
    }

    // ---- tail-zero for next call
    if (t < FF) d_pooled[g * FF + t] = 0.f;
    if (t == 0) d_cnt[g] = 0.f;
    for (int i = g * 128 + t; i < NN; i += GG * 128) d_cnt_in[i] = 0;
    if (g == 0) {
        if (t < 2) d_ssum[t] = 0.f;
        if (t < 128) {
            ((float*)d_fsum)[t] = 0.f; ((float*)d_fsum)[t + 64] = 0.f;
            ((float*)d_fsq)[t]  = 0.f; ((float*)d_fsq)[t + 64]  = 0.f;
        }
        if (t < 64) { ((float*)d_fsum)[128 + t] = 0.f; ((float*)d_fsq)[128 + t] = 0.f; }
    }
}

// ---------------- launch -----------------------------------------------------
extern "C" void kernel_launch(void* const* d_in, const int* in_sizes, int n_in,
                              void* d_out, int out_size) {
    const float* x   = (const float*)d_in[0];
    const int*   ei  = (const int*)d_in[1];
    const int*   bat = (const int*)d_in[2];
    const float* W1  = (const float*)d_in[3];
    const float* g1  = (const float*)d_in[5];
    const float* bt1 = (const float*)d_in[6];
    const float* W2  = (const float*)d_in[7];
    const float* g2  = (const float*)d_in[9];
    const float* bt2 = (const float*)d_in[10];
    const float* W3  = (const float*)d_in[11];
    const float* g3  = (const float*)d_in[13];
    const float* bt3 = (const float*)d_in[14];
    const float* W4  = (const float*)d_in[15];
    const float* g4  = (const float*)d_in[17];
    const float* bt4 = (const float*)d_in[18];
    const float* fw1 = (const float*)d_in[19];
    const float* fb1 = (const float*)d_in[20];
    const float* fw2 = (const float*)d_in[21];
    const float* fb2 = (const float*)d_in[22];
    float* out = (float*)d_out;

    int E_ = in_sizes[1] / 2;
    if (E_ > EE) E_ = EE;

    const int TB = 256;
    int nb_n = (NN + TB - 1) / TB;
    int nb_e = (E_ + TB - 1) / TB;
    int nb_g = (NN + 127) / 128;     // GEMM: 128-row tiles
    const int GATHER_BLKS = 592;

    // CSR build (self-loops embedded in scan; fill is atomic-free via ranks)
    k_count<<<nb_e, TB>>>(ei, E_);
    k_scan<<<1, 1024>>>();
    k_fill<<<nb_e, TB>>>(ei, E_);

    // layer 1 (scalar)
    k_gather1<<<nb_n, TB>>>(x);

    // layer 2
    k_gemm<true><<<nb_g, TB>>>(0, W2, W1, g1, bt1);
    k_gather64<<<GATHER_BLKS, TB>>>(0);

    // layer 3
    k_gemm<false><<<nb_g, TB>>>(0, W3, nullptr, g2, bt2);
    k_gather64<<<GATHER_BLKS, TB>>>(1);

    // layer 4
    k_gemm<false><<<nb_g, TB>>>(1, W4, nullptr, g3, bt3);
    k_gather64<<<GATHER_BLKS, TB>>>(2);

    // pool + head (+ tail-zero)
    k_pool<<<(NN + 255) / 256, TB>>>(bat, g4, bt4);
    k_fc<<<GG, 128>>>(fw1, fb1, fw2, fb2, out);
}

// round 14
// speedup vs baseline: 1.1057x; 1.1057x over previous
#include <cuda_runtime.h>
#include <cuda_fp16.h>
#include <cstdint>

#define NN 50000
#define EE 800000
#define GG 64
#define FF 64
#define BN_EPS 1e-5f

// ---------------- scratch (static device globals; zero-initialized at load) --
// Invariant: d_cnt_in, d_ssum, d_fsum, d_fsq, d_pooled, d_cnt are ZERO at entry
// of every kernel_launch call (static init covers call 1; k_fc tail re-zeros).
__device__ __half d_h[(size_t)NN * FF];    // GEMM output (fp16) / gather source
__device__ float  d_y[(size_t)NN * FF];    // gather output / GEMM input (fp32)
__device__ float  d_s[NN];                 // layer-1 scalar aggregate
__device__ float  d_dinv[NN];              // per-node deg^-1/2 (precomputed!)
__device__ int    d_cnt_in[NN];            // in-degree counters (zeroed in tail)
__device__ int    d_ptr[NN + 1];           // CSR row pointers (by dst)
__device__ int    d_rank[EE];              // per-edge rank within dst row
__device__ int2   d_csr[EE + NN];          // {src, bitcast(norm)}; self incl.
__device__ float  d_ssum[2];               // scalar sum / sumsq (layer 1)
__device__ float  d_fsum[3][FF];           // per-feature sums, layers 2..4
__device__ float  d_fsq[3][FF];
__device__ float  d_pooled[GG * FF];
__device__ float  d_cnt[GG];

// ---------------- setup ------------------------------------------------------
// count AND record rank: the atomic's return value is the edge's slot.
__global__ void k_count(const int* __restrict__ ei, int E_) {
    int e = blockIdx.x * blockDim.x + threadIdx.x;
    if (e < E_) d_rank[e] = atomicAdd(&d_cnt_in[ei[E_ + e]], 1);
}

// single-block exclusive scan of (cnt_in+1) -> d_ptr
__global__ void k_scan() {
    __shared__ int sums[1024];
    int t = threadIdx.x;
    const int CH = (NN + 1023) / 1024;   // 49
    int start = t * CH;
    int end = start + CH; if (end > NN) end = NN;
    int s = 0;
    for (int i = start; i < end; i++) s += d_cnt_in[i] + 1;   // +1 self-loop
    sums[t] = s;
    __syncthreads();
    for (int off = 1; off < 1024; off <<= 1) {
        int v = (t >= off) ? sums[t - off] : 0;
        __syncthreads();
        sums[t] += v;
        __syncthreads();
    }
    int excl = (t == 0) ? 0 : sums[t - 1];
    for (int i = start; i < end; i++) {
        d_ptr[i] = excl;
        excl += d_cnt_in[i] + 1;
    }
    if (t == 1023) d_ptr[NN] = excl;
}

// parallel: dinv (ONE rsqrt per node — keep MUFU off the per-edge path),
// self-loop CSR entry at row head, and layer-1 self-loop init of d_s.
__global__ void k_dinvself(const float* __restrict__ x) {
    int n = blockIdx.x * blockDim.x + threadIdx.x;
    if (n >= NN) return;
    float di = rsqrtf((float)(d_cnt_in[n] + 1));
    float d2 = di * di;
    d_dinv[n] = di;
    d_csr[d_ptr[n]] = make_int2(n, __float_as_int(d2));
    d_s[n] = x[n] * d2;                    // layer-1 self contribution
}

// atomic-free CSR fill (slot = ptr[c] + 1 + rank[e]) + fused layer-1 scatter:
// s[c] += x[r]*nm rides the same random-access pattern fill already owns.
__global__ void k_fill(const int* __restrict__ ei, const float* __restrict__ x, int E_) {
    int e = blockIdx.x * blockDim.x + threadIdx.x;
    if (e >= E_) return;
    int r = ei[e], c = ei[E_ + e];
    float nm = d_dinv[r] * d_dinv[c];
    int p = d_ptr[c] + 1 + d_rank[e];
    d_csr[p] = make_int2(r, __float_as_int(nm));
    atomicAdd(&d_s[c], __ldg(&x[r]) * nm);
}

// ---------------- layer-1 stats: grid-stride reduction of d_s ----------------
__global__ void k_stats_s() {
    float s = 0.f, q = 0.f;
    for (int n = blockIdx.x * blockDim.x + threadIdx.x; n < NN; n += gridDim.x * blockDim.x) {
        float v = d_s[n];
        s += v; q = fmaf(v, v, q);
    }
    for (int o = 16; o; o >>= 1) {
        s += __shfl_down_sync(0xffffffffu, s, o);
        q += __shfl_down_sync(0xffffffffu, q, o);
    }
    __shared__ float sh[2][8];
    int w = threadIdx.x >> 5;
    if ((threadIdx.x & 31) == 0) { sh[0][w] = s; sh[1][w] = q; }
    __syncthreads();
    if (threadIdx.x == 0) {
        s = 0.f; q = 0.f;
        for (int i = 0; i < 8; i++) { s += sh[0][i]; q += sh[1][i]; }
        atomicAdd(&d_ssum[0], s);
        atomicAdd(&d_ssum[1], q);
    }
}

// ---------------- GEMM: 128-row tile, fp16 Z in smem, 8x4 micro-tile --------
// d_h = (half) relu(affine(src)) @ W.  src = d_s (FROM_S) or fp32 d_y.
template <bool FROM_S>
__global__ void __launch_bounds__(256) k_gemm(int L, const float* __restrict__ W,
                       const float* __restrict__ Wp,   // W1 (FROM_S only)
                       const float* __restrict__ g, const float* __restrict__ bt) {
    __shared__ __align__(16) __half Zh[FF][144];   // [k][row], stride 288B
    __shared__ __align__(16) float  Ws[FF][FF];    // 16KB
    __shared__ float sa[FF], sc[FF];
    int t = threadIdx.x;
    int base = blockIdx.x * 128;

    if (t < FF) {
        float inv_n = 1.0f / (float)NN;
        if (FROM_S) {
            float ms = d_ssum[0] * inv_n;
            float vs = d_ssum[1] * inv_n - ms * ms;
            float w1 = Wp[t];
            float ia = g[t] * rsqrtf(vs * w1 * w1 + BN_EPS);
            float A = ia * w1;
            sa[t] = A;
            sc[t] = bt[t] - A * ms;
        } else {
            float m = d_fsum[L][t] * inv_n;
            float v = d_fsq[L][t] * inv_n - m * m;
            float ia = g[t] * rsqrtf(v + BN_EPS);
            sa[t] = ia;
            sc[t] = bt[t] - ia * m;
        }
    }
    {
        const float4* W4 = (const float4*)W;
        float4* Ws4 = (float4*)&Ws[0][0];
        #pragma unroll
        for (int i = 0; i < 4; i++) Ws4[t + i * 256] = W4[t + i * 256];
    }
    __syncthreads();

    // stage Z (fp16): 2 threads per row; thread covers 32 cols
    {
        int lr = t >> 1;                    // 0..127
        int row = base + lr;
        int c0 = (t & 1) * 32;
        if (FROM_S) {
            float sval = (row < NN) ? d_s[row] : 0.f;
            #pragma unroll
            for (int i = 0; i < 32; i++) {
                int cc = c0 + i;
                Zh[cc][lr] = __float2half(fmaxf(sa[cc] * sval + sc[cc], 0.f));
            }
        } else if (row < NN) {
            #pragma unroll
            for (int i = 0; i < 8; i++) {
                int cc = c0 + i * 4;
                float4 v = *(const float4*)(d_y + (size_t)row * FF + cc);
                Zh[cc + 0][lr] = __float2half(fmaxf(sa[cc + 0] * v.x + sc[cc + 0], 0.f));
                Zh[cc + 1][lr] = __float2half(fmaxf(sa[cc + 1] * v.y + sc[cc + 1], 0.f));
                Zh[cc + 2][lr] = __float2half(fmaxf(sa[cc + 2] * v.z + sc[cc + 2], 0.f));
                Zh[cc + 3][lr] = __float2half(fmaxf(sa[cc + 3] * v.w + sc[cc + 3], 0.f));
            }
        } else {
            #pragma unroll
            for (int i = 0; i < 32; i++) Zh[c0 + i][lr] = __float2half(0.f);
        }
    }
    __syncthreads();

    int tx = t & 15, ty = t >> 4;
    float acc[8][4] = {};
    #pragma unroll 8
    for (int k = 0; k < FF; k++) {
        uint4 zu = *(const uint4*)&Zh[k][ty * 8];      // 8 halves = 8 rows
        float4 wv = *(const float4*)&Ws[k][tx * 4];
        const __half2* zh = (const __half2*)&zu;
        float2 z0 = __half22float2(zh[0]);
        float2 z1 = __half22float2(zh[1]);
        float2 z2 = __half22float2(zh[2]);
        float2 z3 = __half22float2(zh[3]);
        float zr[8] = {z0.x, z0.y, z1.x, z1.y, z2.x, z2.y, z3.x, z3.y};
        float wc[4] = {wv.x, wv.y, wv.z, wv.w};
        #pragma unroll
        for (int r = 0; r < 8; r++)
            #pragma unroll
            for (int j = 0; j < 4; j++)
                acc[r][j] = fmaf(zr[r], wc[j], acc[r][j]);
    }
    __syncthreads();    // Zh reads done; reuse as fp16 output stage [128][72]

    __half* zbuf = &Zh[0][0];
    #pragma unroll
    for (int r = 0; r < 8; r++) {
        int sr = ty * 8 + r;
        *(__half2*)&zbuf[sr * 72 + tx * 4]     = __floats2half2_rn(acc[r][0], acc[r][1]);
        *(__half2*)&zbuf[sr * 72 + tx * 4 + 2] = __floats2half2_rn(acc[r][2], acc[r][3]);
    }
    __syncthreads();

    {
        int lr = t >> 1;
        int row = base + lr;
        if (row < NN) {
            int seg = (t & 1) * 32;            // 32 halves = 64B
            const uint4* src = (const uint4*)&zbuf[lr * 72 + seg];
            uint4* dst = (uint4*)(d_h + (size_t)row * FF + seg);
            #pragma unroll
            for (int i = 0; i < 4; i++) dst[i] = src[i];
        }
    }
}

// ---------------- 64-wide gather (fp16 source): 16 threads/node --------------
__global__ void k_gather64(int L) {
    __shared__ float4 smS[8][32];
    __shared__ float4 smQ[8][32];
    int t = threadIdx.x;
    int lane = t & 31, w = t >> 5;          // 8 warps / block
    int fl = lane & 15, sub = lane >> 4;
    float4 rS = make_float4(0.f, 0.f, 0.f, 0.f);
    float4 rQ = make_float4(0.f, 0.f, 0.f, 0.f);
    const uint2* hb = (const uint2*)d_h;    // 16 uint2 (8B) per 64-half row

    for (int n = (blockIdx.x * 8 + w) * 2 + sub; n < NN; n += gridDim.x * 16) {
        int p = d_ptr[n], en = d_ptr[n + 1];
        float4 acc = make_float4(0.f, 0.f, 0.f, 0.f);
        for (; p + 3 < en; p += 4) {
            int2 v0 = __ldg(&d_csr[p]);
            int2 v1 = __ldg(&d_csr[p + 1]);
            int2 v2 = __ldg(&d_csr[p + 2]);
            int2 v3 = __ldg(&d_csr[p + 3]);
            uint2 u0 = __ldg(hb + (size_t)v0.x * 16 + fl);
            uint2 u1 = __ldg(hb + (size_t)v1.x * 16 + fl);
            uint2 u2 = __ldg(hb + (size_t)v2.x * 16 + fl);
            uint2 u3 = __ldg(hb + (size_t)v3.x * 16 + fl);
            float m0 = __int_as_float(v0.y), m1 = __int_as_float(v1.y);
            float m2 = __int_as_float(v2.y), m3 = __int_as_float(v3.y);
            float2 a0 = __half22float2(*(__half2*)&u0.x), b0 = __half22float2(*(__half2*)&u0.y);
            float2 a1 = __half22float2(*(__half2*)&u1.x), b1 = __half22float2(*(__half2*)&u1.y);
            float2 a2 = __half22float2(*(__half2*)&u2.x), b2 = __half22float2(*(__half2*)&u2.y);
            float2 a3 = __half22float2(*(__half2*)&u3.x), b3 = __half22float2(*(__half2*)&u3.y);
            acc.x = fmaf(a0.x, m0, acc.x); acc.y = fmaf(a0.y, m0, acc.y);
            acc.z = fmaf(b0.x, m0, acc.z); acc.w = fmaf(b0.y, m0, acc.w);
            acc.x = fmaf(a1.x, m1, acc.x); acc.y = fmaf(a1.y, m1, acc.y);
            acc.z = fmaf(b1.x, m1, acc.z); acc.w = fmaf(b1.y, m1, acc.w);
            acc.x = fmaf(a2.x, m2, acc.x); acc.y = fmaf(a2.y, m2, acc.y);
            acc.z = fmaf(b2.x, m2, acc.z); acc.w = fmaf(b2.y, m2, acc.w);
            acc.x = fmaf(a3.x, m3, acc.x); acc.y = fmaf(a3.y, m3, acc.y);
            acc.z = fmaf(b3.x, m3, acc.z); acc.w = fmaf(b3.y, m3, acc.w);
        }
        for (; p < en; p++) {
            int2 v = __ldg(&d_csr[p]);
            uint2 u0 = __ldg(hb + (size_t)v.x * 16 + fl);
            float m0 = __int_as_float(v.y);
            float2 a0 = __half22float2(*(__half2*)&u0.x), b0 = __half22float2(*(__half2*)&u0.y);
            acc.x = fmaf(a0.x, m0, acc.x); acc.y = fmaf(a0.y, m0, acc.y);
            acc.z = fmaf(b0.x, m0, acc.z); acc.w = fmaf(b0.y, m0, acc.w);
        }
        ((float4*)(d_y + (size_t)n * FF))[fl] = acc;
        rS.x += acc.x; rS.y += acc.y; rS.z += acc.z; rS.w += acc.w;
        rQ.x = fmaf(acc.x, acc.x, rQ.x); rQ.y = fmaf(acc.y, acc.y, rQ.y);
        rQ.z = fmaf(acc.z, acc.z, rQ.z); rQ.w = fmaf(acc.w, acc.w, rQ.w);
    }
    smS[w][lane] = rS; smQ[w][lane] = rQ;
    __syncthreads();
    if (t < 32) {
        float4 s = make_float4(0.f, 0.f, 0.f, 0.f);
        float4 q = make_float4(0.f, 0.f, 0.f, 0.f);
        #pragma unroll
        for (int i = 0; i < 8; i++) {
            float4 a = smS[i][t], b = smQ[i][t];
            s.x += a.x; s.y += a.y; s.z += a.z; s.w += a.w;
            q.x += b.x; q.y += b.y; q.z += b.z; q.w += b.w;
        }
        s.x += __shfl_down_sync(0xffffffffu, s.x, 16);
        s.y += __shfl_down_sync(0xffffffffu, s.y, 16);
        s.z += __shfl_down_sync(0xffffffffu, s.z, 16);
        s.w += __shfl_down_sync(0xffffffffu, s.w, 16);
        q.x += __shfl_down_sync(0xffffffffu, q.x, 16);
        q.y += __shfl_down_sync(0xffffffffu, q.y, 16);
        q.z += __shfl_down_sync(0xffffffffu, q.z, 16);
        q.w += __shfl_down_sync(0xffffffffu, q.w, 16);
        if (t < 16) {
            atomicAdd(&d_fsum[L][4 * t + 0], s.x);
            atomicAdd(&d_fsum[L][4 * t + 1], s.y);
            atomicAdd(&d_fsum[L][4 * t + 2], s.z);
            atomicAdd(&d_fsum[L][4 * t + 3], s.w);
            atomicAdd(&d_fsq[L][4 * t + 0], q.x);
            atomicAdd(&d_fsq[L][4 * t + 1], q.y);
            atomicAdd(&d_fsq[L][4 * t + 2], q.z);
            atomicAdd(&d_fsq[L][4 * t + 3], q.w);
        }
    }
}

// ---------------- pooling (BN4+ReLU inline) ----------------------------------
__global__ void k_pool(const int* __restrict__ batch,
                       const float* __restrict__ g4, const float* __restrict__ bt4) {
    int t = threadIdx.x;
    int f = t & 63, rg = t >> 6;
    int base = blockIdx.x * 256;
    float inv_n = 1.0f / (float)NN;
    float m = d_fsum[2][f] * inv_n;
    float v = d_fsq[2][f] * inv_n - m * m;
    float ia = g4[f] * rsqrtf(v + BN_EPS);
    float af = ia, cf = bt4[f] - ia * m;
    float acc = 0.f, cacc = 0.f;
    int gcur = -1;
    for (int i = 0; i < 64; i++) {
        int n = base + rg + 4 * i;
        if (n >= NN) break;
        int g = batch[n];
        if (g != gcur) {
            if (gcur >= 0) {
                atomicAdd(&d_pooled[gcur * FF + f], acc);
                if (f == 0) atomicAdd(&d_cnt[gcur], cacc);
            }
            gcur = g; acc = 0.f; cacc = 0.f;
        }
        float vv = fmaxf(af * d_y[(size_t)n * FF + f] + cf, 0.f);
        acc += vv; cacc += 1.f;
    }
    if (gcur >= 0) {
        atomicAdd(&d_pooled[gcur * FF + f], acc);
        if (f == 0) atomicAdd(&d_cnt[gcur], cacc);
    }
}

// ---------------- MLP head: one block per graph, transposed fw1 in smem ------
__global__ void k_fc(const float* __restrict__ fw1, const float* __restrict__ fb1,
                     const float* __restrict__ fw2, const float* __restrict__ fb2,
                     float* __restrict__ out) {
    __shared__ float FWt[FF][129];
    __shared__ float P[FF];
    __shared__ float H[128];
    int t = threadIdx.x;               // 128 threads
    int g = blockIdx.x;                // 64 blocks

    for (int idx = t; idx < 128 * FF; idx += 128) {
        int j = idx >> 6, f = idx & 63;
        FWt[f][j] = fw1[idx];
    }
    if (t < FF) {
        float cc = d_cnt[g]; cc = (cc < 1.f) ? 1.f : cc;
        P[t] = d_pooled[g * FF + t] / cc;
    }
    __syncthreads();

    {
        float s = fb1[t];
        #pragma unroll 16
        for (int f = 0; f < FF; f++) s = fmaf(P[f], FWt[f][t], s);
        H[t] = fmaxf(s, 0.f);
    }
    __syncthreads();

    if (t < 10) {
        float s = fb2[t];
        #pragma unroll 16
        for (int j = 0; j < 128; j++) s = fmaf(H[j], fw2[t * 128 + j], s);
        out[g * 10 + t] = s;
    }

    // ---- tail-zero for next call
    if (t < FF) d_pooled[g * FF + t] = 0.f;
    if (t == 0) d_cnt[g] = 0.f;
    for (int i = g * 128 + t; i < NN; i += GG * 128) d_cnt_in[i] = 0;
    if (g == 0) {
        if (t < 2) d_ssum[t] = 0.f;
        if (t < 128) {
            ((float*)d_fsum)[t] = 0.f; ((float*)d_fsum)[t + 64] = 0.f;
            ((float*)d_fsq)[t]  = 0.f; ((float*)d_fsq)[t + 64]  = 0.f;
        }
        if (t < 64) { ((float*)d_fsum)[128 + t] = 0.f; ((float*)d_fsq)[128 + t] = 0.f; }
    }
}

// ---------------- launch -----------------------------------------------------
extern "C" void kernel_launch(void* const* d_in, const int* in_sizes, int n_in,
                              void* d_out, int out_size) {
    const float* x   = (const float*)d_in[0];
    const int*   ei  = (const int*)d_in[1];
    const int*   bat = (const int*)d_in[2];
    const float* W1  = (const float*)d_in[3];
    const float* g1  = (const float*)d_in[5];
    const float* bt1 = (const float*)d_in[6];
    const float* W2  = (const float*)d_in[7];
    const float* g2  = (const float*)d_in[9];
    const float* bt2 = (const float*)d_in[10];
    const float* W3  = (const float*)d_in[11];
    const float* g3  = (const float*)d_in[13];
    const float* bt3 = (const float*)d_in[14];
    const float* W4  = (const float*)d_in[15];
    const float* g4  = (const float*)d_in[17];
    const float* bt4 = (const float*)d_in[18];
    const float* fw1 = (const float*)d_in[19];
    const float* fb1 = (const float*)d_in[20];
    const float* fw2 = (const float*)d_in[21];
    const float* fb2 = (const float*)d_in[22];
    float* out = (float*)d_out;

    int E_ = in_sizes[1] / 2;
    if (E_ > EE) E_ = EE;

    const int TB = 256;
    int nb_n = (NN + TB - 1) / TB;
    int nb_e = (E_ + TB - 1) / TB;
    int nb_g = (NN + 127) / 128;     // GEMM: 128-row tiles
    const int GATHER_BLKS = 592;

    // CSR build (self-loops via dinvself; fill atomic-free + fused layer-1)
    k_count<<<nb_e, TB>>>(ei, E_);
    k_scan<<<1, 1024>>>();
    k_dinvself<<<nb_n, TB>>>(x);
    k_fill<<<nb_e, TB>>>(ei, x, E_);

    // layer-1 stats only (gather itself happened inside fill)
    k_stats_s<<<128, TB>>>();

    // layer 2
    k_gemm<true><<<nb_g, TB>>>(0, W2, W1, g1, bt1);
    k_gather64<<<GATHER_BLKS, TB>>>(0);

    // layer 3
    k_gemm<false><<<nb_g, TB>>>(0, W3, nullptr, g2, bt2);
    k_gather64<<<GATHER_BLKS, TB>>>(1);

    // layer 4
    k_gemm<false><<<nb_g, TB>>>(1, W4, nullptr, g3, bt3);
    k_gather64<<<GATHER_BLKS, TB>>>(2);

    // pool + head (+ tail-zero)
    k_pool<<<(NN + 255) / 256, TB>>>(bat, g4, bt4);
    k_fc<<<GG, 128>>>(fw1, fb1, fw2, fb2, out);
}

// round 15
// speedup vs baseline: 1.1272x; 1.0195x over previous
#include <cuda_runtime.h>
#include <cuda_fp16.h>
#include <cstdint>

#define NN 50000
#define EE 800000
#define GG 64
#define FF 64
#define BN_EPS 1e-5f

// ---------------- scratch (static device globals; zero-initialized at load) --
// Invariant: d_cnt_in, d_ssum, d_fsum, d_fsq, d_pooled, d_cnt are ZERO at entry
// of every kernel_launch call (static init covers call 1; k_fc tail re-zeros).
__device__ __half d_h[(size_t)NN * FF];    // GEMM output (fp16) / gather source
__device__ float  d_y[(size_t)NN * FF];    // gather output / GEMM input (fp32)
__device__ float  d_s[NN];                 // layer-1 scalar aggregate
__device__ float  d_dinv[NN];              // per-node deg^-1/2 (precomputed)
__device__ int    d_cnt_in[NN];            // in-degree counters (zeroed in tail)
__device__ int    d_ptr[NN + 1];           // CSR row pointers (by dst)
__device__ int    d_rank[EE];              // per-edge rank within dst row
__device__ int2   d_csr[EE + NN];          // {src, bitcast(norm)}; self incl.
__device__ float  d_ssum[2];               // scalar sum / sumsq (layer 1)
__device__ float  d_fsum[3][FF];           // per-feature sums, layers 2..4
__device__ float  d_fsq[3][FF];
__device__ float  d_pooled[GG * FF];
__device__ float  d_cnt[GG];

// ---------------- PDL helpers -------------------------------------------------
// griddepcontrol.wait: block until the PDL-predecessor grid's writes are
// visible. No-op when the kernel was launched without a PDL edge.
__device__ __forceinline__ void grid_dep_wait() {
    asm volatile("griddepcontrol.wait;" ::: "memory");
}

// ---------------- setup ------------------------------------------------------
// count AND record rank: the atomic's return value is the edge's slot.
__global__ void k_count(const int* __restrict__ ei, int E_) {
    int e = blockIdx.x * blockDim.x + threadIdx.x;
    if (e < E_) d_rank[e] = atomicAdd(&d_cnt_in[ei[E_ + e]], 1);
}

// single-block exclusive scan of (cnt_in+1) -> d_ptr
__global__ void k_scan() {
    __shared__ int sums[1024];
    int t = threadIdx.x;
    grid_dep_wait();
    const int CH = (NN + 1023) / 1024;   // 49
    int start = t * CH;
    int end = start + CH; if (end > NN) end = NN;
    int s = 0;
    for (int i = start; i < end; i++) s += d_cnt_in[i] + 1;   // +1 self-loop
    sums[t] = s;
    __syncthreads();
    for (int off = 1; off < 1024; off <<= 1) {
        int v = (t >= off) ? sums[t - off] : 0;
        __syncthreads();
        sums[t] += v;
        __syncthreads();
    }
    int excl = (t == 0) ? 0 : sums[t - 1];
    for (int i = start; i < end; i++) {
        d_ptr[i] = excl;
        excl += d_cnt_in[i] + 1;
    }
    if (t == 1023) d_ptr[NN] = excl;
}

// parallel: dinv (ONE rsqrt per node), self-loop CSR entry, layer-1 self init.
// Prologue loads x[n] (harness input) before the PDL wait.
__global__ void k_dinvself(const float* __restrict__ x) {
    int n = blockIdx.x * blockDim.x + threadIdx.x;
    float xv = (n < NN) ? __ldg(&x[n]) : 0.f;   // input-only prologue
    grid_dep_wait();
    if (n >= NN) return;
    float di = rsqrtf((float)(d_cnt_in[n] + 1));
    float d2 = di * di;
    d_dinv[n] = di;
    d_csr[d_ptr[n]] = make_int2(n, __float_as_int(d2));
    d_s[n] = xv * d2;                      // layer-1 self contribution
}

// atomic-free CSR fill (slot = ptr[c] + 1 + rank[e]) + fused layer-1 scatter.
// Prologue loads ei / x[r] (inputs) before the PDL wait.
__global__ void k_fill(const int* __restrict__ ei, const float* __restrict__ x, int E_) {
    int e = blockIdx.x * blockDim.x + threadIdx.x;
    int r = 0, c = 0; float xr = 0.f;
    if (e < E_) {
        r = __ldg(&ei[e]); c = __ldg(&ei[E_ + e]);
        xr = __ldg(&x[r]);                 // input-only prologue
    }
    grid_dep_wait();
    if (e >= E_) return;
    float nm = d_dinv[r] * d_dinv[c];
    int p = d_ptr[c] + 1 + d_rank[e];
    d_csr[p] = make_int2(r, __float_as_int(nm));
    atomicAdd(&d_s[c], xr * nm);
}

// ---------------- layer-1 stats: grid-stride reduction of d_s ----------------
__global__ void k_stats_s() {
    grid_dep_wait();
    float s = 0.f, q = 0.f;
    for (int n = blockIdx.x * blockDim.x + threadIdx.x; n < NN; n += gridDim.x * blockDim.x) {
        float v = d_s[n];
        s += v; q = fmaf(v, v, q);
    }
    for (int o = 16; o; o >>= 1) {
        s += __shfl_down_sync(0xffffffffu, s, o);
        q += __shfl_down_sync(0xffffffffu, q, o);
    }
    __shared__ float sh[2][8];
    int w = threadIdx.x >> 5;
    if ((threadIdx.x & 31) == 0) { sh[0][w] = s; sh[1][w] = q; }
    __syncthreads();
    if (threadIdx.x == 0) {
        s = 0.f; q = 0.f;
        for (int i = 0; i < 8; i++) { s += sh[0][i]; q += sh[1][i]; }
        atomicAdd(&d_ssum[0], s);
        atomicAdd(&d_ssum[1], q);
    }
}

// ---------------- GEMM: 128-row tile, fp16 Z in smem, 8x4 micro-tile --------
// d_h = (half) relu(affine(src)) @ W.  src = d_s (FROM_S) or fp32 d_y.
// Prologue: stage W (input) into smem BEFORE the PDL wait.
template <bool FROM_S>
__global__ void __launch_bounds__(256) k_gemm(int L, const float* __restrict__ W,
                       const float* __restrict__ Wp,   // W1 (FROM_S only)
                       const float* __restrict__ g, const float* __restrict__ bt) {
    __shared__ __align__(16) __half Zh[FF][144];   // [k][row], stride 288B
    __shared__ __align__(16) float  Ws[FF][FF];    // 16KB
    __shared__ float sa[FF], sc[FF];
    int t = threadIdx.x;
    int base = blockIdx.x * 128;

    {   // input-only prologue: W into smem
        const float4* W4 = (const float4*)W;
        float4* Ws4 = (float4*)&Ws[0][0];
        #pragma unroll
        for (int i = 0; i < 4; i++) Ws4[t + i * 256] = W4[t + i * 256];
    }
    float w1v = 0.f, gv = 0.f, btv = 0.f;
    if (t < FF) {
        gv = __ldg(&g[t]); btv = __ldg(&bt[t]);
        if (FROM_S) w1v = __ldg(&Wp[t]);
    }

    grid_dep_wait();   // predecessor's stats / activations now visible

    if (t < FF) {
        float inv_n = 1.0f / (float)NN;
        if (FROM_S) {
            float ms = d_ssum[0] * inv_n;
            float vs = d_ssum[1] * inv_n - ms * ms;
            float ia = gv * rsqrtf(vs * w1v * w1v + BN_EPS);
            float A = ia * w1v;
            sa[t] = A;
            sc[t] = btv - A * ms;
        } else {
            float m = d_fsum[L][t] * inv_n;
            float v = d_fsq[L][t] * inv_n - m * m;
            float ia = gv * rsqrtf(v + BN_EPS);
            sa[t] = ia;
            sc[t] = btv - ia * m;
        }
    }
    __syncthreads();

    // stage Z (fp16): 2 threads per row; thread covers 32 cols
    {
        int lr = t >> 1;                    // 0..127
        int row = base + lr;
        int c0 = (t & 1) * 32;
        if (FROM_S) {
            float sval = (row < NN) ? d_s[row] : 0.f;
            #pragma unroll
            for (int i = 0; i < 32; i++) {
                int cc = c0 + i;
                Zh[cc][lr] = __float2half(fmaxf(sa[cc] * sval + sc[cc], 0.f));
            }
        } else if (row < NN) {
            #pragma unroll
            for (int i = 0; i < 8; i++) {
                int cc = c0 + i * 4;
                float4 v = *(const float4*)(d_y + (size_t)row * FF + cc);
                Zh[cc + 0][lr] = __float2half(fmaxf(sa[cc + 0] * v.x + sc[cc + 0], 0.f));
                Zh[cc + 1][lr] = __float2half(fmaxf(sa[cc + 1] * v.y + sc[cc + 1], 0.f));
                Zh[cc + 2][lr] = __float2half(fmaxf(sa[cc + 2] * v.z + sc[cc + 2], 0.f));
                Zh[cc + 3][lr] = __float2half(fmaxf(sa[cc + 3] * v.w + sc[cc + 3], 0.f));
            }
        } else {
            #pragma unroll
            for (int i = 0; i < 32; i++) Zh[c0 + i][lr] = __float2half(0.f);
        }
    }
    __syncthreads();

    int tx = t & 15, ty = t >> 4;
    float acc[8][4] = {};
    #pragma unroll 8
    for (int k = 0; k < FF; k++) {
        uint4 zu = *(const uint4*)&Zh[k][ty * 8];      // 8 halves = 8 rows
        float4 wv = *(const float4*)&Ws[k][tx * 4];
        const __half2* zh = (const __half2*)&zu;
        float2 z0 = __half22float2(zh[0]);
        float2 z1 = __half22float2(zh[1]);
        float2 z2 = __half22float2(zh[2]);
        float2 z3 = __half22float2(zh[3]);
        float zr[8] = {z0.x, z0.y, z1.x, z1.y, z2.x, z2.y, z3.x, z3.y};
        float wc[4] = {wv.x, wv.y, wv.z, wv.w};
        #pragma unroll
        for (int r = 0; r < 8; r++)
            #pragma unroll
            for (int j = 0; j < 4; j++)
                acc[r][j] = fmaf(zr[r], wc[j], acc[r][j]);
    }
    __syncthreads();    // Zh reads done; reuse as fp16 output stage [128][72]

    __half* zbuf = &Zh[0][0];
    #pragma unroll
    for (int r = 0; r < 8; r++) {
        int sr = ty * 8 + r;
        *(__half2*)&zbuf[sr * 72 + tx * 4]     = __floats2half2_rn(acc[r][0], acc[r][1]);
        *(__half2*)&zbuf[sr * 72 + tx * 4 + 2] = __floats2half2_rn(acc[r][2], acc[r][3]);
    }
    __syncthreads();

    {
        int lr = t >> 1;
        int row = base + lr;
        if (row < NN) {
            int seg = (t & 1) * 32;            // 32 halves = 64B
            const uint4* src = (const uint4*)&zbuf[lr * 72 + seg];
            uint4* dst = (uint4*)(d_h + (size_t)row * FF + seg);
            #pragma unroll
            for (int i = 0; i < 4; i++) dst[i] = src[i];
        }
    }
}

// ---------------- 64-wide gather (fp16 source): 16 threads/node --------------
__global__ void k_gather64(int L) {
    __shared__ float4 smS[8][32];
    __shared__ float4 smQ[8][32];
    int t = threadIdx.x;
    int lane = t & 31, w = t >> 5;          // 8 warps / block
    int fl = lane & 15, sub = lane >> 4;
    grid_dep_wait();
    float4 rS = make_float4(0.f, 0.f, 0.f, 0.f);
    float4 rQ = make_float4(0.f, 0.f, 0.f, 0.f);
    const uint2* hb = (const uint2*)d_h;    // 16 uint2 (8B) per 64-half row

    for (int n = (blockIdx.x * 8 + w) * 2 + sub; n < NN; n += gridDim.x * 16) {
        int p = d_ptr[n], en = d_ptr[n + 1];
        float4 acc = make_float4(0.f, 0.f, 0.f, 0.f);
        for (; p + 3 < en; p += 4) {
            int2 v0 = __ldg(&d_csr[p]);
            int2 v1 = __ldg(&d_csr[p + 1]);
            int2 v2 = __ldg(&d_csr[p + 2]);
            int2 v3 = __ldg(&d_csr[p + 3]);
            uint2 u0 = __ldg(hb + (size_t)v0.x * 16 + fl);
            uint2 u1 = __ldg(hb + (size_t)v1.x * 16 + fl);
            uint2 u2 = __ldg(hb + (size_t)v2.x * 16 + fl);
            uint2 u3 = __ldg(hb + (size_t)v3.x * 16 + fl);
            float m0 = __int_as_float(v0.y), m1 = __int_as_float(v1.y);
            float m2 = __int_as_float(v2.y), m3 = __int_as_float(v3.y);
            float2 a0 = __half22float2(*(__half2*)&u0.x), b0 = __half22float2(*(__half2*)&u0.y);
            float2 a1 = __half22float2(*(__half2*)&u1.x), b1 = __half22float2(*(__half2*)&u1.y);
            float2 a2 = __half22float2(*(__half2*)&u2.x), b2 = __half22float2(*(__half2*)&u2.y);
            float2 a3 = __half22float2(*(__half2*)&u3.x), b3 = __half22float2(*(__half2*)&u3.y);
            acc.x = fmaf(a0.x, m0, acc.x); acc.y = fmaf(a0.y, m0, acc.y);
            acc.z = fmaf(b0.x, m0, acc.z); acc.w = fmaf(b0.y, m0, acc.w);
            acc.x = fmaf(a1.x, m1, acc.x); acc.y = fmaf(a1.y, m1, acc.y);
            acc.z = fmaf(b1.x, m1, acc.z); acc.w = fmaf(b1.y, m1, acc.w);
            acc.x = fmaf(a2.x, m2, acc.x); acc.y = fmaf(a2.y, m2, acc.y);
            acc.z = fmaf(b2.x, m2, acc.z); acc.w = fmaf(b2.y, m2, acc.w);
            acc.x = fmaf(a3.x, m3, acc.x); acc.y = fmaf(a3.y, m3, acc.y);
            acc.z = fmaf(b3.x, m3, acc.z); acc.w = fmaf(b3.y, m3, acc.w);
        }
        for (; p < en; p++) {
            int2 v = __ldg(&d_csr[p]);
            uint2 u0 = __ldg(hb + (size_t)v.x * 16 + fl);
            float m0 = __int_as_float(v.y);
            float2 a0 = __half22float2(*(__half2*)&u0.x), b0 = __half22float2(*(__half2*)&u0.y);
            acc.x = fmaf(a0.x, m0, acc.x); acc.y = fmaf(a0.y, m0, acc.y);
            acc.z = fmaf(b0.x, m0, acc.z); acc.w = fmaf(b0.y, m0, acc.w);
        }
        ((float4*)(d_y + (size_t)n * FF))[fl] = acc;
        rS.x += acc.x; rS.y += acc.y; rS.z += acc.z; rS.w += acc.w;
        rQ.x = fmaf(acc.x, acc.x, rQ.x); rQ.y = fmaf(acc.y, acc.y, rQ.y);
        rQ.z = fmaf(acc.z, acc.z, rQ.z); rQ.w = fmaf(acc.w, acc.w, rQ.w);
    }
    smS[w][lane] = rS; smQ[w][lane] = rQ;
    __syncthreads();
    if (t < 32) {
        float4 s = make_float4(0.f, 0.f, 0.f, 0.f);
        float4 q = make_float4(0.f, 0.f, 0.f, 0.f);
        #pragma unroll
        for (int i = 0; i < 8; i++) {
            float4 a = smS[i][t], b = smQ[i][t];
            s.x += a.x; s.y += a.y; s.z += a.z; s.w += a.w;
            q.x += b.x; q.y += b.y; q.z += b.z; q.w += b.w;
        }
        s.x += __shfl_down_sync(0xffffffffu, s.x, 16);
        s.y += __shfl_down_sync(0xffffffffu, s.y, 16);
        s.z += __shfl_down_sync(0xffffffffu, s.z, 16);
        s.w += __shfl_down_sync(0xffffffffu, s.w, 16);
        q.x += __shfl_down_sync(0xffffffffu, q.x, 16);
        q.y += __shfl_down_sync(0xffffffffu, q.y, 16);
        q.z += __shfl_down_sync(0xffffffffu, q.z, 16);
        q.w += __shfl_down_sync(0xffffffffu, q.w, 16);
        if (t < 16) {
            atomicAdd(&d_fsum[L][4 * t + 0], s.x);
            atomicAdd(&d_fsum[L][4 * t + 1], s.y);
            atomicAdd(&d_fsum[L][4 * t + 2], s.z);
            atomicAdd(&d_fsum[L][4 * t + 3], s.w);
            atomicAdd(&d_fsq[L][4 * t + 0], q.x);
            atomicAdd(&d_fsq[L][4 * t + 1], q.y);
            atomicAdd(&d_fsq[L][4 * t + 2], q.z);
            atomicAdd(&d_fsq[L][4 * t + 3], q.w);
        }
    }
}

// ---------------- pooling (BN4+ReLU inline) ----------------------------------
__global__ void k_pool(const int* __restrict__ batch,
                       const float* __restrict__ g4, const float* __restrict__ bt4) {
    int t = threadIdx.x;
    int f = t & 63, rg = t >> 6;
    int base = blockIdx.x * 256;
    float gv = __ldg(&g4[f]), btv = __ldg(&bt4[f]);   // input-only prologue
    grid_dep_wait();
    float inv_n = 1.0f / (float)NN;
    float m = d_fsum[2][f] * inv_n;
    float v = d_fsq[2][f] * inv_n - m * m;
    float ia = gv * rsqrtf(v + BN_EPS);
    float af = ia, cf = btv - ia * m;
    float acc = 0.f, cacc = 0.f;
    int gcur = -1;
    for (int i = 0; i < 64; i++) {
        int n = base + rg + 4 * i;
        if (n >= NN) break;
        int g = batch[n];
        if (g != gcur) {
            if (gcur >= 0) {
                atomicAdd(&d_pooled[gcur * FF + f], acc);
                if (f == 0) atomicAdd(&d_cnt[gcur], cacc);
            }
            gcur = g; acc = 0.f; cacc = 0.f;
        }
        float vv = fmaxf(af * d_y[(size_t)n * FF + f] + cf, 0.f);
        acc += vv; cacc += 1.f;
    }
    if (gcur >= 0) {
        atomicAdd(&d_pooled[gcur * FF + f], acc);
        if (f == 0) atomicAdd(&d_cnt[gcur], cacc);
    }
}

// ---------------- MLP head: one block per graph, transposed fw1 in smem ------
__global__ void k_fc(const float* __restrict__ fw1, const float* __restrict__ fb1,
                     const float* __restrict__ fw2, const float* __restrict__ fb2,
                     float* __restrict__ out) {
    __shared__ float FWt[FF][129];
    __shared__ float P[FF];
    __shared__ float H[128];
    int t = threadIdx.x;               // 128 threads
    int g = blockIdx.x;                // 64 blocks

    // input-only prologue: stage fw1 transposed
    for (int idx = t; idx < 128 * FF; idx += 128) {
        int j = idx >> 6, f = idx & 63;
        FWt[f][j] = fw1[idx];
    }
    grid_dep_wait();

    if (t < FF) {
        float cc = d_cnt[g]; cc = (cc < 1.f) ? 1.f : cc;
        P[t] = d_pooled[g * FF + t] / cc;
    }
    __syncthreads();

    {
        float s = fb1[t];
        #pragma unroll 16
        for (int f = 0; f < FF; f++) s = fmaf(P[f], FWt[f][t], s);
        H[t] = fmaxf(s, 0.f);
    }
    __syncthreads();

    if (t < 10) {
        float s = fb2[t];
        #pragma unroll 16
        for (int j = 0; j < 128; j++) s = fmaf(H[j], fw2[t * 128 + j], s);
        out[g * 10 + t] = s;
    }

    // ---- tail-zero for next call
    if (t < FF) d_pooled[g * FF + t] = 0.f;
    if (t == 0) d_cnt[g] = 0.f;
    for (int i = g * 128 + t; i < NN; i += GG * 128) d_cnt_in[i] = 0;
    if (g == 0) {
        if (t < 2) d_ssum[t] = 0.f;
        if (t < 128) {
            ((float*)d_fsum)[t] = 0.f; ((float*)d_fsum)[t + 64] = 0.f;
            ((float*)d_fsq)[t]  = 0.f; ((float*)d_fsq)[t + 64]  = 0.f;
        }
        if (t < 64) { ((float*)d_fsum)[128 + t] = 0.f; ((float*)d_fsq)[128 + t] = 0.f; }
    }
}

// ---------------- launch -----------------------------------------------------
extern "C" void kernel_launch(void* const* d_in, const int* in_sizes, int n_in,
                              void* d_out, int out_size) {
    const float* x   = (const float*)d_in[0];
    const int*   ei  = (const int*)d_in[1];
    const int*   bat = (const int*)d_in[2];
    const float* W1  = (const float*)d_in[3];
    const float* g1  = (const float*)d_in[5];
    const float* bt1 = (const float*)d_in[6];
    const float* W2  = (const float*)d_in[7];
    const float* g2  = (const float*)d_in[9];
    const float* bt2 = (const float*)d_in[10];
    const float* W3  = (const float*)d_in[11];
    const float* g3  = (const float*)d_in[13];
    const float* bt3 = (const float*)d_in[14];
    const float* W4  = (const float*)d_in[15];
    const float* g4  = (const float*)d_in[17];
    const float* bt4 = (const float*)d_in[18];
    const float* fw1 = (const float*)d_in[19];
    const float* fb1 = (const float*)d_in[20];
    const float* fw2 = (const float*)d_in[21];
    const float* fb2 = (const float*)d_in[22];
    float* out = (float*)d_out;

    int E_ = in_sizes[1] / 2;
    if (E_ > EE) E_ = EE;

    const int TB = 256;
    int nb_n = (NN + TB - 1) / TB;
    int nb_e = (E_ + TB - 1) / TB;
    int nb_g = (NN + 127) / 128;     // GEMM: 128-row tiles
    const int GATHER_BLKS = 592;

    // PDL launch config (same legacy stream as <<<>>>)
    cudaLaunchAttribute pdl_attr;
    pdl_attr.id = cudaLaunchAttributeProgrammaticStreamSerialization;
    pdl_attr.val.programmaticStreamSerializationAllowed = 1;
    cudaLaunchConfig_t cfg = {};
    cfg.blockDim = dim3(TB, 1, 1);
    cfg.dynamicSmemBytes = 0;
    cfg.stream = 0;
    cfg.attrs = &pdl_attr;
    cfg.numAttrs = 1;

    // CSR build: first kernel launches normally
    k_count<<<nb_e, TB>>>(ei, E_);

    cfg.gridDim = dim3(1, 1, 1); cfg.blockDim = dim3(1024, 1, 1);
    cudaLaunchKernelEx(&cfg, k_scan);

    cfg.blockDim = dim3(TB, 1, 1);
    cfg.gridDim = dim3(nb_n, 1, 1);
    cudaLaunchKernelEx(&cfg, k_dinvself, x);

    cfg.gridDim = dim3(nb_e, 1, 1);
    cudaLaunchKernelEx(&cfg, k_fill, ei, x, E_);

    cfg.gridDim = dim3(128, 1, 1);
    cudaLaunchKernelEx(&cfg, k_stats_s);

    // layer 2
    cfg.gridDim = dim3(nb_g, 1, 1);
    cudaLaunchKernelEx(&cfg, k_gemm<true>, 0, W2, W1, g1, bt1);
    cfg.gridDim = dim3(GATHER_BLKS, 1, 1);
    cudaLaunchKernelEx(&cfg, k_gather64, 0);

    // layer 3
    cfg.gridDim = dim3(nb_g, 1, 1);
    cudaLaunchKernelEx(&cfg, k_gemm<false>, 0, W3, (const float*)nullptr, g2, bt2);
    cfg.gridDim = dim3(GATHER_BLKS, 1, 1);
    cudaLaunchKernelEx(&cfg, k_gather64, 1);

    // layer 4
    cfg.gridDim = dim3(nb_g, 1, 1);
    cudaLaunchKernelEx(&cfg, k_gemm<false>, 1, W4, (const float*)nullptr, g3, bt3);
    cfg.gridDim = dim3(GATHER_BLKS, 1, 1);
    cudaLaunchKernelEx(&cfg, k_gather64, 2);

    // pool + head (+ tail-zero)
    cfg.gridDim = dim3((NN + 255) / 256, 1, 1);
    cudaLaunchKernelEx(&cfg, k_pool, bat, g4, bt4);

    cfg.gridDim = dim3(GG, 1, 1); cfg.blockDim = dim3(128, 1, 1);
    cudaLaunchKernelEx(&cfg, k_fc, fw1, fb1, fw2, fb2, out);
}

// round 16
// speedup vs baseline: 1.3534x; 1.2007x over previous
#include <cuda_runtime.h>
#include <cuda_fp16.h>
#include <cstdint>

#define NN 50000
#define EE 800000
#define GG 64
#define FF 64
#define BN_EPS 1e-5f

// ---------------- scratch (static device globals; zero-initialized at load) --
// Invariant: d_cnt_in, d_ssum, d_fsum, d_fsq, d_pooled, d_cnt are ZERO at entry
// of every kernel_launch call (static init covers call 1; k_fc tail re-zeros).
__device__ __half d_h[(size_t)NN * FF];    // GEMM output (fp16) / gather source
__device__ float  d_y[(size_t)NN * FF];    // gather output / GEMM input (fp32)
__device__ float  d_s[NN];                 // layer-1 scalar aggregate
__device__ float  d_dinv[NN];              // per-node deg^-1/2 (precomputed)
__device__ int    d_cnt_in[NN];            // in-degree counters (zeroed in tail)
__device__ int    d_ptr[NN + 1];           // CSR row pointers (by dst)
__device__ int    d_rank[EE];              // per-edge rank within dst row
__device__ int2   d_csr[EE + NN];          // {src, bitcast(norm)}; self incl.
__device__ float  d_ssum[2];               // scalar sum / sumsq (layer 1)
__device__ float  d_fsum[3][FF];           // per-feature sums, layers 2..4
__device__ float  d_fsq[3][FF];
__device__ float  d_pooled[GG * FF];
__device__ float  d_cnt[GG];

// ---------------- PDL helpers -------------------------------------------------
__device__ __forceinline__ void grid_dep_wait() {
    asm volatile("griddepcontrol.wait;" ::: "memory");
}

// ---------------- setup ------------------------------------------------------
__global__ void k_count(const int* __restrict__ ei, int E_) {
    int e = blockIdx.x * blockDim.x + threadIdx.x;
    if (e < E_) d_rank[e] = atomicAdd(&d_cnt_in[ei[E_ + e]], 1);
}

__global__ void k_scan() {
    __shared__ int sums[1024];
    int t = threadIdx.x;
    grid_dep_wait();
    const int CH = (NN + 1023) / 1024;   // 49
    int start = t * CH;
    int end = start + CH; if (end > NN) end = NN;
    int s = 0;
    for (int i = start; i < end; i++) s += d_cnt_in[i] + 1;   // +1 self-loop
    sums[t] = s;
    __syncthreads();
    for (int off = 1; off < 1024; off <<= 1) {
        int v = (t >= off) ? sums[t - off] : 0;
        __syncthreads();
        sums[t] += v;
        __syncthreads();
    }
    int excl = (t == 0) ? 0 : sums[t - 1];
    for (int i = start; i < end; i++) {
        d_ptr[i] = excl;
        excl += d_cnt_in[i] + 1;
    }
    if (t == 1023) d_ptr[NN] = excl;
}

__global__ void k_dinvself(const float* __restrict__ x) {
    int n = blockIdx.x * blockDim.x + threadIdx.x;
    float xv = (n < NN) ? __ldg(&x[n]) : 0.f;
    grid_dep_wait();
    if (n >= NN) return;
    float di = rsqrtf((float)(d_cnt_in[n] + 1));
    float d2 = di * di;
    d_dinv[n] = di;
    d_csr[d_ptr[n]] = make_int2(n, __float_as_int(d2));
    d_s[n] = xv * d2;
}

__global__ void k_fill(const int* __restrict__ ei, const float* __restrict__ x, int E_) {
    int e = blockIdx.x * blockDim.x + threadIdx.x;
    int r = 0, c = 0; float xr = 0.f;
    if (e < E_) {
        r = __ldg(&ei[e]); c = __ldg(&ei[E_ + e]);
        xr = __ldg(&x[r]);
    }
    grid_dep_wait();
    if (e >= E_) return;
    float nm = d_dinv[r] * d_dinv[c];
    int p = d_ptr[c] + 1 + d_rank[e];
    d_csr[p] = make_int2(r, __float_as_int(nm));
    atomicAdd(&d_s[c], xr * nm);
}

// ---------------- layer-1 stats ----------------------------------------------
__global__ void k_stats_s() {
    grid_dep_wait();
    float s = 0.f, q = 0.f;
    for (int n = blockIdx.x * blockDim.x + threadIdx.x; n < NN; n += gridDim.x * blockDim.x) {
        float v = d_s[n];
        s += v; q = fmaf(v, v, q);
    }
    for (int o = 16; o; o >>= 1) {
        s += __shfl_down_sync(0xffffffffu, s, o);
        q += __shfl_down_sync(0xffffffffu, q, o);
    }
    __shared__ float sh[2][8];
    int w = threadIdx.x >> 5;
    if ((threadIdx.x & 31) == 0) { sh[0][w] = s; sh[1][w] = q; }
    __syncthreads();
    if (threadIdx.x == 0) {
        s = 0.f; q = 0.f;
        for (int i = 0; i < 8; i++) { s += sh[0][i]; q += sh[1][i]; }
        atomicAdd(&d_ssum[0], s);
        atomicAdd(&d_ssum[1], q);
    }
}

// ---------------- GEMM: 128-row tile, fp16 Z in smem, 8x4 micro-tile --------
template <bool FROM_S>
__global__ void __launch_bounds__(256) k_gemm(int L, const float* __restrict__ W,
                       const float* __restrict__ Wp,
                       const float* __restrict__ g, const float* __restrict__ bt) {
    __shared__ __align__(16) __half Zh[FF][144];
    __shared__ __align__(16) float  Ws[FF][FF];
    __shared__ float sa[FF], sc[FF];
    int t = threadIdx.x;
    int base = blockIdx.x * 128;

    {   // input-only prologue
        const float4* W4 = (const float4*)W;
        float4* Ws4 = (float4*)&Ws[0][0];
        #pragma unroll
        for (int i = 0; i < 4; i++) Ws4[t + i * 256] = W4[t + i * 256];
    }
    float w1v = 0.f, gv = 0.f, btv = 0.f;
    if (t < FF) {
        gv = __ldg(&g[t]); btv = __ldg(&bt[t]);
        if (FROM_S) w1v = __ldg(&Wp[t]);
    }

    grid_dep_wait();

    if (t < FF) {
        float inv_n = 1.0f / (float)NN;
        if (FROM_S) {
            float ms = d_ssum[0] * inv_n;
            float vs = d_ssum[1] * inv_n - ms * ms;
            float ia = gv * rsqrtf(vs * w1v * w1v + BN_EPS);
            float A = ia * w1v;
            sa[t] = A;
            sc[t] = btv - A * ms;
        } else {
            float m = d_fsum[L][t] * inv_n;
            float v = d_fsq[L][t] * inv_n - m * m;
            float ia = gv * rsqrtf(v + BN_EPS);
            sa[t] = ia;
            sc[t] = btv - ia * m;
        }
    }
    __syncthreads();

    {
        int lr = t >> 1;
        int row = base + lr;
        int c0 = (t & 1) * 32;
        if (FROM_S) {
            float sval = (row < NN) ? d_s[row] : 0.f;
            #pragma unroll
            for (int i = 0; i < 32; i++) {
                int cc = c0 + i;
                Zh[cc][lr] = __float2half(fmaxf(sa[cc] * sval + sc[cc], 0.f));
            }
        } else if (row < NN) {
            #pragma unroll
            for (int i = 0; i < 8; i++) {
                int cc = c0 + i * 4;
                float4 v = *(const float4*)(d_y + (size_t)row * FF + cc);
                Zh[cc + 0][lr] = __float2half(fmaxf(sa[cc + 0] * v.x + sc[cc + 0], 0.f));
                Zh[cc + 1][lr] = __float2half(fmaxf(sa[cc + 1] * v.y + sc[cc + 1], 0.f));
                Zh[cc + 2][lr] = __float2half(fmaxf(sa[cc + 2] * v.z + sc[cc + 2], 0.f));
                Zh[cc + 3][lr] = __float2half(fmaxf(sa[cc + 3] * v.w + sc[cc + 3], 0.f));
            }
        } else {
            #pragma unroll
            for (int i = 0; i < 32; i++) Zh[c0 + i][lr] = __float2half(0.f);
        }
    }
    __syncthreads();

    int tx = t & 15, ty = t >> 4;
    float acc[8][4] = {};
    #pragma unroll 8
    for (int k = 0; k < FF; k++) {
        uint4 zu = *(const uint4*)&Zh[k][ty * 8];
        float4 wv = *(const float4*)&Ws[k][tx * 4];
        const __half2* zh = (const __half2*)&zu;
        float2 z0 = __half22float2(zh[0]);
        float2 z1 = __half22float2(zh[1]);
        float2 z2 = __half22float2(zh[2]);
        float2 z3 = __half22float2(zh[3]);
        float zr[8] = {z0.x, z0.y, z1.x, z1.y, z2.x, z2.y, z3.x, z3.y};
        float wc[4] = {wv.x, wv.y, wv.z, wv.w};
        #pragma unroll
        for (int r = 0; r < 8; r++)
            #pragma unroll
            for (int j = 0; j < 4; j++)
                acc[r][j] = fmaf(zr[r], wc[j], acc[r][j]);
    }
    __syncthreads();

    __half* zbuf = &Zh[0][0];
    #pragma unroll
    for (int r = 0; r < 8; r++) {
        int sr = ty * 8 + r;
        *(__half2*)&zbuf[sr * 72 + tx * 4]     = __floats2half2_rn(acc[r][0], acc[r][1]);
        *(__half2*)&zbuf[sr * 72 + tx * 4 + 2] = __floats2half2_rn(acc[r][2], acc[r][3]);
    }
    __syncthreads();

    {
        int lr = t >> 1;
        int row = base + lr;
        if (row < NN) {
            int seg = (t & 1) * 32;
            const uint4* src = (const uint4*)&zbuf[lr * 72 + seg];
            uint4* dst = (uint4*)(d_h + (size_t)row * FF + seg);
            #pragma unroll
            for (int i = 0; i < 4; i++) dst[i] = src[i];
        }
    }
}

// ---------------- 64-wide gather: 8 lanes/node, uint4 (16B) per lane ---------
// Lane fl = lane&7 owns halves [8fl, 8fl+8); sub = lane>>3 picks one of 4
// concurrent nodes per warp. 4-deep unroll -> 16 independent h-lines in
// flight per warp (2x the previous 16-lane layout).
__global__ void k_gather64(int L) {
    __shared__ float smS[8][64];
    __shared__ float smQ[8][64];
    int t = threadIdx.x;
    int lane = t & 31, w = t >> 5;          // 8 warps / block
    int fl = lane & 7, sub = lane >> 3;     // 4 nodes / warp
    grid_dep_wait();
    float rS[8] = {}, rQ[8] = {};
    const uint4* hb = (const uint4*)d_h;    // 8 uint4 (16B) per 64-half row

    for (int n = (blockIdx.x * 8 + w) * 4 + sub; n < NN; n += gridDim.x * 32) {
        int p = d_ptr[n], en = d_ptr[n + 1];
        float acc[8] = {};
        for (; p + 3 < en; p += 4) {
            int2 v0 = __ldg(&d_csr[p]);
            int2 v1 = __ldg(&d_csr[p + 1]);
            int2 v2 = __ldg(&d_csr[p + 2]);
            int2 v3 = __ldg(&d_csr[p + 3]);
            uint4 u0 = __ldg(hb + (size_t)v0.x * 8 + fl);
            uint4 u1 = __ldg(hb + (size_t)v1.x * 8 + fl);
            uint4 u2 = __ldg(hb + (size_t)v2.x * 8 + fl);
            uint4 u3 = __ldg(hb + (size_t)v3.x * 8 + fl);
            float m0 = __int_as_float(v0.y), m1 = __int_as_float(v1.y);
            float m2 = __int_as_float(v2.y), m3 = __int_as_float(v3.y);
            const __half2* h0 = (const __half2*)&u0;
            const __half2* h1 = (const __half2*)&u1;
            const __half2* h2 = (const __half2*)&u2;
            const __half2* h3 = (const __half2*)&u3;
            #pragma unroll
            for (int i = 0; i < 4; i++) {
                float2 f0 = __half22float2(h0[i]);
                float2 f1 = __half22float2(h1[i]);
                float2 f2 = __half22float2(h2[i]);
                float2 f3 = __half22float2(h3[i]);
                acc[2*i]   = fmaf(f0.x, m0, acc[2*i]);
                acc[2*i+1] = fmaf(f0.y, m0, acc[2*i+1]);
                acc[2*i]   = fmaf(f1.x, m1, acc[2*i]);
                acc[2*i+1] = fmaf(f1.y, m1, acc[2*i+1]);
                acc[2*i]   = fmaf(f2.x, m2, acc[2*i]);
                acc[2*i+1] = fmaf(f2.y, m2, acc[2*i+1]);
                acc[2*i]   = fmaf(f3.x, m3, acc[2*i]);
                acc[2*i+1] = fmaf(f3.y, m3, acc[2*i+1]);
            }
        }
        for (; p < en; p++) {
            int2 v = __ldg(&d_csr[p]);
            uint4 u0 = __ldg(hb + (size_t)v.x * 8 + fl);
            float m0 = __int_as_float(v.y);
            const __half2* h0 = (const __half2*)&u0;
            #pragma unroll
            for (int i = 0; i < 4; i++) {
                float2 f0 = __half22float2(h0[i]);
                acc[2*i]   = fmaf(f0.x, m0, acc[2*i]);
                acc[2*i+1] = fmaf(f0.y, m0, acc[2*i+1]);
            }
        }
        // store 8 floats (32B) per lane: two STG.128
        float4* yrow = (float4*)(d_y + (size_t)n * FF + 8 * fl);
        yrow[0] = make_float4(acc[0], acc[1], acc[2], acc[3]);
        yrow[1] = make_float4(acc[4], acc[5], acc[6], acc[7]);
        #pragma unroll
        for (int i = 0; i < 8; i++) {
            rS[i] += acc[i];
            rQ[i] = fmaf(acc[i], acc[i], rQ[i]);
        }
    }
    // fold the 4 subs (lanes fl, fl+8, fl+16, fl+24 share features)
    #pragma unroll
    for (int i = 0; i < 8; i++) {
        rS[i] += __shfl_down_sync(0xffffffffu, rS[i], 16);
        rS[i] += __shfl_down_sync(0xffffffffu, rS[i], 8);
        rQ[i] += __shfl_down_sync(0xffffffffu, rQ[i], 16);
        rQ[i] += __shfl_down_sync(0xffffffffu, rQ[i], 8);
    }
    if (lane < 8) {
        #pragma unroll
        for (int i = 0; i < 8; i++) {
            smS[w][8 * fl + i] = rS[i];
            smQ[w][8 * fl + i] = rQ[i];
        }
    }
    __syncthreads();
    if (t < 64) {
        float s = 0.f, q = 0.f;
        #pragma unroll
        for (int i = 0; i < 8; i++) { s += smS[i][t]; q += smQ[i][t]; }
        atomicAdd(&d_fsum[L][t], s);
        atomicAdd(&d_fsq[L][t], q);
    }
}

// ---------------- pooling (BN4+ReLU inline) ----------------------------------
__global__ void k_pool(const int* __restrict__ batch,
                       const float* __restrict__ g4, const float* __restrict__ bt4) {
    int t = threadIdx.x;
    int f = t & 63, rg = t >> 6;
    int base = blockIdx.x * 256;
    float gv = __ldg(&g4[f]), btv = __ldg(&bt4[f]);
    grid_dep_wait();
    float inv_n = 1.0f / (float)NN;
    float m = d_fsum[2][f] * inv_n;
    float v = d_fsq[2][f] * inv_n - m * m;
    float ia = gv * rsqrtf(v + BN_EPS);
    float af = ia, cf = btv - ia * m;
    float acc = 0.f, cacc = 0.f;
    int gcur = -1;
    for (int i = 0; i < 64; i++) {
        int n = base + rg + 4 * i;
        if (n >= NN) break;
        int g = batch[n];
        if (g != gcur) {
            if (gcur >= 0) {
                atomicAdd(&d_pooled[gcur * FF + f], acc);
                if (f == 0) atomicAdd(&d_cnt[gcur], cacc);
            }
            gcur = g; acc = 0.f; cacc = 0.f;
        }
        float vv = fmaxf(af * d_y[(size_t)n * FF + f] + cf, 0.f);
        acc += vv; cacc += 1.f;
    }
    if (gcur >= 0) {
        atomicAdd(&d_pooled[gcur * FF + f], acc);
        if (f == 0) atomicAdd(&d_cnt[gcur], cacc);
    }
}

// ---------------- MLP head ----------------------------------------------------
__global__ void k_fc(const float* __restrict__ fw1, const float* __restrict__ fb1,
                     const float* __restrict__ fw2, const float* __restrict__ fb2,
                     float* __restrict__ out) {
    __shared__ float FWt[FF][129];
    __shared__ float P[FF];
    __shared__ float H[128];
    int t = threadIdx.x;               // 128 threads
    int g = blockIdx.x;                // 64 blocks

    for (int idx = t; idx < 128 * FF; idx += 128) {
        int j = idx >> 6, f = idx & 63;
        FWt[f][j] = fw1[idx];
    }
    grid_dep_wait();

    if (t < FF) {
        float cc = d_cnt[g]; cc = (cc < 1.f) ? 1.f : cc;
        P[t] = d_pooled[g * FF + t] / cc;
    }
    __syncthreads();

    {
        float s = fb1[t];
        #pragma unroll 16
        for (int f = 0; f < FF; f++) s = fmaf(P[f], FWt[f][t], s);
        H[t] = fmaxf(s, 0.f);
    }
    __syncthreads();

    if (t < 10) {
        float s = fb2[t];
        #pragma unroll 16
        for (int j = 0; j < 128; j++) s = fmaf(H[j], fw2[t * 128 + j], s);
        out[g * 10 + t] = s;
    }

    // ---- tail-zero for next call
    if (t < FF) d_pooled[g * FF + t] = 0.f;
    if (t == 0) d_cnt[g] = 0.f;
    for (int i = g * 128 + t; i < NN; i += GG * 128) d_cnt_in[i] = 0;
    if (g == 0) {
        if (t < 2) d_ssum[t] = 0.f;
        if (t < 128) {
            ((float*)d_fsum)[t] = 0.f; ((float*)d_fsum)[t + 64] = 0.f;
            ((float*)d_fsq)[t]  = 0.f; ((float*)d_fsq)[t + 64]  = 0.f;
        }
        if (t < 64) { ((float*)d_fsum)[128 + t] = 0.f; ((float*)d_fsq)[128 + t] = 0.f; }
    }
}

// ---------------- launch -----------------------------------------------------
extern "C" void kernel_launch(void* const* d_in, const int* in_sizes, int n_in,
                              void* d_out, int out_size) {
    const float* x   = (const float*)d_in[0];
    const int*   ei  = (const int*)d_in[1];
    const int*   bat = (const int*)d_in[2];
    const float* W1  = (const float*)d_in[3];
    const float* g1  = (const float*)d_in[5];
    const float* bt1 = (const float*)d_in[6];
    const float* W2  = (const float*)d_in[7];
    const float* g2  = (const float*)d_in[9];
    const float* bt2 = (const float*)d_in[10];
    const float* W3  = (const float*)d_in[11];
    const float* g3  = (const float*)d_in[13];
    const float* bt3 = (const float*)d_in[14];
    const float* W4  = (const float*)d_in[15];
    const float* g4  = (const float*)d_in[17];
    const float* bt4 = (const float*)d_in[18];
    const float* fw1 = (const float*)d_in[19];
    const float* fb1 = (const float*)d_in[20];
    const float* fw2 = (const float*)d_in[21];
    const float* fb2 = (const float*)d_in[22];
    float* out = (float*)d_out;

    int E_ = in_sizes[1] / 2;
    if (E_ > EE) E_ = EE;

    const int TB = 256;
    int nb_n = (NN + TB - 1) / TB;
    int nb_e = (E_ + TB - 1) / TB;
    int nb_g = (NN + 127) / 128;
    const int GATHER_BLKS = 592;

    cudaLaunchAttribute pdl_attr;
    pdl_attr.id = cudaLaunchAttributeProgrammaticStreamSerialization;
    pdl_attr.val.programmaticStreamSerializationAllowed = 1;
    cudaLaunchConfig_t cfg = {};
    cfg.blockDim = dim3(TB, 1, 1);
    cfg.dynamicSmemBytes = 0;
    cfg.stream = 0;
    cfg.attrs = &pdl_attr;
    cfg.numAttrs = 1;

    k_count<<<nb_e, TB>>>(ei, E_);

    cfg.gridDim = dim3(1, 1, 1); cfg.blockDim = dim3(1024, 1, 1);
    cudaLaunchKernelEx(&cfg, k_scan);

    cfg.blockDim = dim3(TB, 1, 1);
    cfg.gridDim = dim3(nb_n, 1, 1);
    cudaLaunchKernelEx(&cfg, k_dinvself, x);

    cfg.gridDim = dim3(nb_e, 1, 1);
    cudaLaunchKernelEx(&cfg, k_fill, ei, x, E_);

    cfg.gridDim = dim3(128, 1, 1);
    cudaLaunchKernelEx(&cfg, k_stats_s);

    // layer 2
    cfg.gridDim = dim3(nb_g, 1, 1);
    cudaLaunchKernelEx(&cfg, k_gemm<true>, 0, W2, W1, g1, bt1);
    cfg.gridDim = dim3(GATHER_BLKS, 1, 1);
    cudaLaunchKernelEx(&cfg, k_gather64, 0);

    // layer 3
    cfg.gridDim = dim3(nb_g, 1, 1);
    cudaLaunchKernelEx(&cfg, k_gemm<false>, 0, W3, (const float*)nullptr, g2, bt2);
    cfg.gridDim = dim3(GATHER_BLKS, 1, 1);
    cudaLaunchKernelEx(&cfg, k_gather64, 1);

    // layer 4
    cfg.gridDim = dim3(nb_g, 1, 1);
    cudaLaunchKernelEx(&cfg, k_gemm<false>, 1, W4, (const float*)nullptr, g3, bt3);
    cfg.gridDim = dim3(GATHER_BLKS, 1, 1);
    cudaLaunchKernelEx(&cfg, k_gather64, 2);

    // pool + head (+ tail-zero)
    cfg.gridDim = dim3((NN + 255) / 256, 1, 1);
    cudaLaunchKernelEx(&cfg, k_pool, bat, g4, bt4);

    cfg.gridDim = dim3(GG, 1, 1); cfg.blockDim = dim3(128, 1, 1);
    cudaLaunchKernelEx(&cfg, k_fc, fw1, fb1, fw2, fb2, out);
}